// round 2
// baseline (speedup 1.0000x reference)
#include <cuda_runtime.h>

#define NN 100000
#define EE 1600000
#define SCAN_BLK 512
#define NSCAN ((NN + SCAN_BLK - 1) / SCAN_BLK)   // 196

// ---------------- static device scratch (no allocation allowed) -------------
__device__ float  g_H [NN * 32];   // recurrent state h (cols 26..31 kept zero)
__device__ float  g_H1[NN * 32];
__device__ float  g_H2[NN * 32];
__device__ float2 g_csr[EE];       // (norm, (float)src) sorted by dst
__device__ int    g_off[NN + 1];
__device__ int    g_cnt[NN];
__device__ int    g_cur[NN];
__device__ float  g_dis[NN];       // rsqrt(deg)
__device__ float  g_selfn[NN];     // dis^2 = self-loop norm
__device__ float  g_xa[NN];        // aggregated x (time-invariant)
__device__ float  g_sn[NN];        // aggregated norm row-sum (time-invariant)
__device__ int    g_bsum[1024];
__device__ int    g_is64;          // edge_index dtype flag (1 = int64, 0 = int32)

// ---------------- dtype probe ----------------------------------------------
// JAX default config demotes int64 -> int32; detect actual width on device.
// If the buffer really holds int64 node ids, the first 16 values are < NN.
// If it holds int32 ids, each int64 read aliases two ids: lo + hi*2^32, which
// is >= 2^32 unless hi == 0 (prob ~(1/NN)^16 across 16 probes).
__global__ void detect_k(const void* ei) {
    const long long* p = (const long long*)ei;
    int is64 = 1;
    for (int i = 0; i < 16; i++) {
        long long v = p[i];
        if (v < 0 || v >= NN) { is64 = 0; break; }
    }
    g_is64 = is64;
}

__device__ __forceinline__ int edge_at(const void* ei, int idx) {
    if (g_is64) return (int)((const long long*)ei)[idx];
    return ((const int*)ei)[idx];
}

// ---------------- preprocessing -------------------------------------------
__global__ void zero_k() {
    int i = blockIdx.x * blockDim.x + threadIdx.x;
    if (i < NN) { g_cnt[i] = 0; g_cur[i] = 0; }
}

__global__ void count_k(const void* __restrict__ ei, int E) {
    int i = blockIdx.x * blockDim.x + threadIdx.x;
    if (i < E) {
        int d = edge_at(ei, E + i);          // dst row
        if ((unsigned)d < NN) atomicAdd(&g_cnt[d], 1);
    }
}

__global__ void deg_k() {
    int i = blockIdx.x * blockDim.x + threadIdx.x;
    if (i < NN) {
        float d = (float)(g_cnt[i] + 1);     // +1 self loop
        float r = rsqrtf(d);
        g_dis[i] = r;
        g_selfn[i] = r * r;
    }
}

__global__ void scan1_k() {
    __shared__ int s[SCAN_BLK];
    int i = blockIdx.x * SCAN_BLK + threadIdx.x;
    s[threadIdx.x] = (i < NN) ? g_cnt[i] : 0;
    __syncthreads();
    for (int o = 1; o < SCAN_BLK; o <<= 1) {
        int u = (threadIdx.x >= o) ? s[threadIdx.x - o] : 0;
        __syncthreads();
        s[threadIdx.x] += u;
        __syncthreads();
    }
    if (i < NN) g_off[i + 1] = s[threadIdx.x];          // block-local inclusive
    if (threadIdx.x == SCAN_BLK - 1) g_bsum[blockIdx.x] = s[SCAN_BLK - 1];
}

__global__ void scan2_k(int nb) {
    __shared__ int s[256];
    int tid = threadIdx.x;
    s[tid] = (tid < nb) ? g_bsum[tid] : 0;
    __syncthreads();
    for (int o = 1; o < 256; o <<= 1) {
        int u = (tid >= o) ? s[tid - o] : 0;
        __syncthreads();
        s[tid] += u;
        __syncthreads();
    }
    int ex = (tid == 0) ? 0 : s[tid - 1];
    __syncthreads();
    if (tid < nb) g_bsum[tid] = ex;                      // exclusive block offsets
}

__global__ void scan3_k() {
    int i = blockIdx.x * SCAN_BLK + threadIdx.x;
    if (i < NN) g_off[i + 1] += g_bsum[blockIdx.x];
    if (i == 0) g_off[0] = 0;
}

__global__ void scatter_k(const void* __restrict__ ei, int E) {
    int i = blockIdx.x * blockDim.x + threadIdx.x;
    if (i < E) {
        int s = edge_at(ei, i);
        int d = edge_at(ei, E + i);
        if ((unsigned)s < NN && (unsigned)d < NN) {
            int p = g_off[d] + atomicAdd(&g_cur[d], 1);
            g_csr[p] = make_float2(g_dis[s] * g_dis[d], (float)s);  // exact: s < 2^24
        }
    }
}

// time-invariant aggregates of x and of the norm row-sum
__global__ void xasn_k(const float* __restrict__ x) {
    int w = (blockIdx.x * blockDim.x + threadIdx.x) >> 5;
    int lane = threadIdx.x & 31;
    if (w >= NN) return;
    int beg = g_off[w], end = g_off[w + 1];
    float sn = 0.f, xa = 0.f;
    for (int e = beg + lane; e < end; e += 32) {
        float2 c = g_csr[e];
        sn += c.x;
        xa = fmaf(c.x, __ldg(&x[(int)c.y]), xa);
    }
    for (int o = 16; o; o >>= 1) {
        sn += __shfl_down_sync(0xffffffffu, sn, o);
        xa += __shfl_down_sync(0xffffffffu, xa, o);
    }
    if (lane == 0) {
        float s0 = g_selfn[w];
        g_sn[w] = s0 + sn;
        g_xa[w] = fmaf(s0, __ldg(&x[w]), xa);
    }
}

// h = relu(relu(y0 @ fc1 + b1) @ fc2 + b2), stored padded to 32 cols (26..31 = 0)
__global__ void inith_k(const float* __restrict__ y,
                        const float* __restrict__ w1, const float* __restrict__ b1,
                        const float* __restrict__ w2, const float* __restrict__ b2) {
    __shared__ float s1w[32], s1b[32], s2w[32 * 26], s2b[26];
    int tid = threadIdx.x;
    if (tid < 32) { s1w[tid] = w1[tid]; s1b[tid] = b1[tid]; }
    if (tid < 26) s2b[tid] = b2[tid];
    for (int i = tid; i < 32 * 26; i += blockDim.x) s2w[i] = w2[i];
    __syncthreads();
    int n = blockIdx.x * blockDim.x + tid;
    if (n >= NN) return;
    float y0 = y[n];
    float h0[32];
#pragma unroll
    for (int k = 0; k < 32; k++) h0[k] = fmaxf(fmaf(y0, s1w[k], s1b[k]), 0.f);
#pragma unroll 2
    for (int j = 0; j < 26; j++) {
        float v = s2b[j];
#pragma unroll
        for (int k = 0; k < 32; k++) v = fmaf(h0[k], s2w[k * 26 + j], v);
        g_H[n * 32 + j] = fmaxf(v, 0.f);
    }
#pragma unroll
    for (int j = 26; j < 32; j++) g_H[n * 32 + j] = 0.f;
}

__global__ void row0_k(float* __restrict__ out, const float* __restrict__ y) {
    int i = blockIdx.x * blockDim.x + threadIdx.x;
    if (i < NN) out[i] = y[i];
}

// ---------------- main-loop GCN layers -------------------------------------
// warp-per-node gather of 32-wide features; CSR entries loaded lane-parallel
// then broadcast via shfl so the feature gathers are independent (high MLP).
__device__ __forceinline__ float gather32(const float* __restrict__ Hin,
                                          int node, int lane) {
    float acc = g_selfn[node] * __ldg(&Hin[node * 32 + lane]);
    int beg = g_off[node], end = g_off[node + 1];
    for (int base = beg; base < end; base += 32) {
        int m = min(32, end - base);
        float nrm = 0.f; int sidx = 0;
        if (lane < m) {
            float2 c = g_csr[base + lane];
            nrm = c.x; sidx = (int)c.y;
        }
#pragma unroll 4
        for (int e = 0; e < m; e++) {
            float nb = __shfl_sync(0xffffffffu, nrm, e);
            int   sb = __shfl_sync(0xffffffffu, sidx, e);
            acc = fmaf(nb, __ldg(&Hin[sb * 32 + lane]), acc);
        }
    }
    return acc;
}

__global__ __launch_bounds__(256) void conv1_k(const float* __restrict__ W,
                                               const float* __restrict__ b,
                                               const float* __restrict__ tarr,
                                               int step) {
    __shared__ float sW[1024], sAgg[8][32], swx[32], swt[32], sb[32];
    int tid = threadIdx.x;
    for (int i = tid; i < 1024; i += 256) sW[i] = W[i];
    if (tid < 32) {
        sb[tid]  = b[tid];
        swx[tid] = W[26 * 32 + tid] + W[27 * 32 + tid] + W[28 * 32 + tid];
        swt[tid] = W[29 * 32 + tid] + W[30 * 32 + tid] + W[31 * 32 + tid];
    }
    __syncthreads();
    int w = tid >> 5, lane = tid & 31;
    int node = blockIdx.x * 8 + w;
    if (node >= NN) return;
    float acc = gather32(g_H, node, lane);   // cols 26..31 of g_H are zero
    sAgg[w][lane] = acc;
    __syncwarp();
    float o = sb[lane];
#pragma unroll
    for (int c = 0; c < 32; c++) o = fmaf(sAgg[w][c], sW[c * 32 + lane], o);
    float tv = __ldg(&tarr[step]);
    o = fmaf(g_xa[node], swx[lane], o);
    o = fmaf(tv * g_sn[node], swt[lane], o);
    g_H1[node * 32 + lane] = fmaxf(o, 0.f);
}

__global__ __launch_bounds__(256) void conv2_k(const float* __restrict__ W,
                                               const float* __restrict__ b) {
    __shared__ float sW[1024], sAgg[8][32], sb[32];
    int tid = threadIdx.x;
    for (int i = tid; i < 1024; i += 256) sW[i] = W[i];
    if (tid < 32) sb[tid] = b[tid];
    __syncthreads();
    int w = tid >> 5, lane = tid & 31;
    int node = blockIdx.x * 8 + w;
    if (node >= NN) return;
    float acc = gather32(g_H1, node, lane);
    sAgg[w][lane] = acc;
    __syncwarp();
    float o = sb[lane];
#pragma unroll
    for (int c = 0; c < 32; c++) o = fmaf(sAgg[w][c], sW[c * 32 + lane], o);
    g_H2[node * 32 + lane] = fmaxf(o, 0.f);
}

// conv3 (32->26) fused with fc3(26->32)+relu+fc4(32->1) readout
__global__ __launch_bounds__(256) void conv3_k(const float* __restrict__ W,
                                               const float* __restrict__ b,
                                               const float* __restrict__ f3w,
                                               const float* __restrict__ f3b,
                                               const float* __restrict__ f4w,
                                               const float* __restrict__ f4b,
                                               float* __restrict__ out, int step) {
    __shared__ float sW[1024], sF3[832], sAgg[8][32], sb[32], sb3[32], sf4[32];
    int tid = threadIdx.x;
    for (int i = tid; i < 1024; i += 256) {
        int r = i >> 5, c = i & 31;
        sW[i] = (c < 26) ? W[r * 26 + c] : 0.f;          // pad cols 26..31
    }
    for (int i = tid; i < 832; i += 256) sF3[i] = f3w[i];
    if (tid < 32) {
        sb[tid]  = (tid < 26) ? b[tid] : 0.f;
        sb3[tid] = f3b[tid];
        sf4[tid] = f4w[tid];
    }
    __syncthreads();
    int w = tid >> 5, lane = tid & 31;
    int node = blockIdx.x * 8 + w;
    if (node >= NN) return;
    float acc = gather32(g_H2, node, lane);
    sAgg[w][lane] = acc;
    __syncwarp();
    float o = sb[lane];
#pragma unroll
    for (int c = 0; c < 32; c++) o = fmaf(sAgg[w][c], sW[c * 32 + lane], o);
    float h3 = fmaxf(o, 0.f);                            // lanes>=26 -> 0
    if (lane < 26) g_H[node * 32 + lane] = h3;           // next recurrent state
    __syncwarp();
    sAgg[w][lane] = (lane < 26) ? h3 : 0.f;
    __syncwarp();
    float z = sb3[lane];
#pragma unroll
    for (int j = 0; j < 26; j++) z = fmaf(sAgg[w][j], sF3[j * 32 + lane], z);
    z = fmaxf(z, 0.f);
    float p = z * sf4[lane];
#pragma unroll
    for (int o2 = 16; o2; o2 >>= 1) p += __shfl_down_sync(0xffffffffu, p, o2);
    if (lane == 0) out[step * NN + node] = p + __ldg(&f4b[0]);
}

// ---------------- launcher --------------------------------------------------
extern "C" void kernel_launch(void* const* d_in, const int* in_sizes, int n_in,
                              void* d_out, int out_size) {
    const float* x  = (const float*)d_in[0];
    const float* t  = (const float*)d_in[1];
    const float* y  = (const float*)d_in[2];
    const void*  ei = d_in[3];                 // int32 or int64 — probed on device
    const float* fc1W = (const float*)d_in[4];
    const float* fc1b = (const float*)d_in[5];
    const float* fc2W = (const float*)d_in[6];
    const float* fc2b = (const float*)d_in[7];
    const float* c1W  = (const float*)d_in[8];
    const float* c1b  = (const float*)d_in[9];
    const float* c2W  = (const float*)d_in[10];
    const float* c2b  = (const float*)d_in[11];
    const float* c3W  = (const float*)d_in[12];
    const float* c3b  = (const float*)d_in[13];
    const float* f3W  = (const float*)d_in[14];
    const float* f3b  = (const float*)d_in[15];
    const float* f4W  = (const float*)d_in[16];
    const float* f4b  = (const float*)d_in[17];
    float* out = (float*)d_out;

    int T = in_sizes[1];
    int E = in_sizes[3] / 2;

    // ---- per-call preprocessing: dtype probe, CSR build, invariants ----
    detect_k<<<1, 1>>>(ei);
    zero_k<<<(NN + 255) / 256, 256>>>();
    count_k<<<(E + 255) / 256, 256>>>(ei, E);
    deg_k<<<(NN + 255) / 256, 256>>>();
    scan1_k<<<NSCAN, SCAN_BLK>>>();
    scan2_k<<<1, 256>>>(NSCAN);
    scan3_k<<<NSCAN, SCAN_BLK>>>();
    scatter_k<<<(E + 255) / 256, 256>>>(ei, E);
    xasn_k<<<(NN * 32 + 255) / 256, 256>>>(x);
    inith_k<<<(NN + 255) / 256, 256>>>(y, fc1W, fc1b, fc2W, fc2b);
    row0_k<<<(NN + 255) / 256, 256>>>(out, y);

    // ---- 49 recurrent steps, 3 fused GCN kernels each ----
    int grid = (NN + 7) / 8;
    for (int s = 1; s < T; s++) {
        conv1_k<<<grid, 256>>>(c1W, c1b, t, s);
        conv2_k<<<grid, 256>>>(c2W, c2b);
        conv3_k<<<grid, 256>>>(c3W, c3b, f3W, f3b, f4W, f4b, out, s);
    }
}

// round 5
// speedup vs baseline: 1.1109x; 1.1109x over previous
#include <cuda_runtime.h>

#define NN 100000
#define EE 1600000
#define SCAN_BLK 512
#define NSCAN ((NN + SCAN_BLK - 1) / SCAN_BLK)   // 196
#define NPB 32                                    // nodes per block (8 warps x 4)

// ---------------- static device scratch (no allocation allowed) -------------
__device__ float  g_H [NN * 32];   // recurrent state h (cols 26..31 kept zero)
__device__ float  g_H1[NN * 32];
__device__ float  g_H2[NN * 32];
__device__ int2   g_csr[EE];       // (norm bits, src) sorted by dst
__device__ int    g_off[NN + 1];
__device__ int    g_cnt[NN];
__device__ int    g_cur[NN];
__device__ float  g_dis[NN];       // rsqrt(deg)
__device__ float  g_selfn[NN];     // dis^2 = self-loop norm
__device__ float  g_xa[NN];        // aggregated x (time-invariant)
__device__ float  g_sn[NN];        // aggregated norm row-sum (time-invariant)
__device__ int    g_bsum[1024];
__device__ int    g_is64;          // edge_index dtype flag (1 = int64, 0 = int32)

// ---------------- dtype probe ----------------------------------------------
__global__ void detect_k(const void* ei) {
    const long long* p = (const long long*)ei;
    int is64 = 1;
    for (int i = 0; i < 16; i++) {
        long long v = p[i];
        if (v < 0 || v >= NN) { is64 = 0; break; }
    }
    g_is64 = is64;
}

__device__ __forceinline__ int edge_at(const void* ei, int idx) {
    if (g_is64) return (int)((const long long*)ei)[idx];
    return ((const int*)ei)[idx];
}

// ---------------- preprocessing -------------------------------------------
__global__ void zero_k() {
    int i = blockIdx.x * blockDim.x + threadIdx.x;
    if (i < NN) { g_cnt[i] = 0; g_cur[i] = 0; }
}

__global__ void count_k(const void* __restrict__ ei, int E) {
    int i = blockIdx.x * blockDim.x + threadIdx.x;
    if (i < E) {
        int d = edge_at(ei, E + i);
        if ((unsigned)d < NN) atomicAdd(&g_cnt[d], 1);
    }
}

__global__ void deg_k() {
    int i = blockIdx.x * blockDim.x + threadIdx.x;
    if (i < NN) {
        float d = (float)(g_cnt[i] + 1);     // +1 self loop
        float r = rsqrtf(d);
        g_dis[i] = r;
        g_selfn[i] = r * r;
    }
}

__global__ void scan1_k() {
    __shared__ int s[SCAN_BLK];
    int i = blockIdx.x * SCAN_BLK + threadIdx.x;
    s[threadIdx.x] = (i < NN) ? g_cnt[i] : 0;
    __syncthreads();
    for (int o = 1; o < SCAN_BLK; o <<= 1) {
        int u = (threadIdx.x >= o) ? s[threadIdx.x - o] : 0;
        __syncthreads();
        s[threadIdx.x] += u;
        __syncthreads();
    }
    if (i < NN) g_off[i + 1] = s[threadIdx.x];
    if (threadIdx.x == SCAN_BLK - 1) g_bsum[blockIdx.x] = s[SCAN_BLK - 1];
}

__global__ void scan2_k(int nb) {
    __shared__ int s[256];
    int tid = threadIdx.x;
    s[tid] = (tid < nb) ? g_bsum[tid] : 0;
    __syncthreads();
    for (int o = 1; o < 256; o <<= 1) {
        int u = (tid >= o) ? s[tid - o] : 0;
        __syncthreads();
        s[tid] += u;
        __syncthreads();
    }
    int ex = (tid == 0) ? 0 : s[tid - 1];
    __syncthreads();
    if (tid < nb) g_bsum[tid] = ex;
}

__global__ void scan3_k() {
    int i = blockIdx.x * SCAN_BLK + threadIdx.x;
    if (i < NN) g_off[i + 1] += g_bsum[blockIdx.x];
    if (i == 0) g_off[0] = 0;
}

__global__ void scatter_k(const void* __restrict__ ei, int E) {
    int i = blockIdx.x * blockDim.x + threadIdx.x;
    if (i < E) {
        int s = edge_at(ei, i);
        int d = edge_at(ei, E + i);
        if ((unsigned)s < NN && (unsigned)d < NN) {
            int p = g_off[d] + atomicAdd(&g_cur[d], 1);
            g_csr[p] = make_int2(__float_as_int(g_dis[s] * g_dis[d]), s);
        }
    }
}

// time-invariant aggregates of x and of the norm row-sum
__global__ void xasn_k(const float* __restrict__ x) {
    int w = (blockIdx.x * blockDim.x + threadIdx.x) >> 5;
    int lane = threadIdx.x & 31;
    if (w >= NN) return;
    int beg = g_off[w], end = g_off[w + 1];
    float sn = 0.f, xa = 0.f;
    for (int e = beg + lane; e < end; e += 32) {
        int2 c = g_csr[e];
        float nm = __int_as_float(c.x);
        sn += nm;
        xa = fmaf(nm, __ldg(&x[c.y]), xa);
    }
    for (int o = 16; o; o >>= 1) {
        sn += __shfl_down_sync(0xffffffffu, sn, o);
        xa += __shfl_down_sync(0xffffffffu, xa, o);
    }
    if (lane == 0) {
        float s0 = g_selfn[w];
        g_sn[w] = s0 + sn;
        g_xa[w] = fmaf(s0, __ldg(&x[w]), xa);
    }
}

// h = relu(relu(y0 @ fc1 + b1) @ fc2 + b2), padded to 32 cols (26..31 = 0)
__global__ void inith_k(const float* __restrict__ y,
                        const float* __restrict__ w1, const float* __restrict__ b1,
                        const float* __restrict__ w2, const float* __restrict__ b2) {
    __shared__ float s1w[32], s1b[32], s2w[32 * 26], s2b[26];
    int tid = threadIdx.x;
    if (tid < 32) { s1w[tid] = w1[tid]; s1b[tid] = b1[tid]; }
    if (tid < 26) s2b[tid] = b2[tid];
    for (int i = tid; i < 32 * 26; i += blockDim.x) s2w[i] = w2[i];
    __syncthreads();
    int n = blockIdx.x * blockDim.x + tid;
    if (n >= NN) return;
    float y0 = y[n];
    float h0[32];
#pragma unroll
    for (int k = 0; k < 32; k++) h0[k] = fmaxf(fmaf(y0, s1w[k], s1b[k]), 0.f);
#pragma unroll 2
    for (int j = 0; j < 26; j++) {
        float v = s2b[j];
#pragma unroll
        for (int k = 0; k < 32; k++) v = fmaf(h0[k], s2w[k * 26 + j], v);
        g_H[n * 32 + j] = fmaxf(v, 0.f);
    }
#pragma unroll
    for (int j = 26; j < 32; j++) g_H[n * 32 + j] = 0.f;
}

__global__ void row0_k(float* __restrict__ out, const float* __restrict__ y) {
    int i = blockIdx.x * blockDim.x + threadIdx.x;
    if (i < NN) out[i] = y[i];
}

// ---------------- main-loop gather -----------------------------------------
// 8 lanes per edge, 4 edges in flight per warp iteration. Each lane owns
// feature quarter q = lane&7 (float4) and edge subgroup g = lane>>3.
// Returns: every lane holds the full aggregate for its feature quarter.
__device__ __forceinline__ float4 gather4(const float4* __restrict__ Hin4,
                                          int node, int lane) {
    int q = lane & 7;
    int g = lane >> 3;
    float4 acc = make_float4(0.f, 0.f, 0.f, 0.f);
    if (g == 0) {                            // self loop handled by subgroup 0
        float s0 = g_selfn[node];
        float4 v = __ldg(&Hin4[node * 8 + q]);
        acc.x = s0 * v.x; acc.y = s0 * v.y; acc.z = s0 * v.z; acc.w = s0 * v.w;
    }
    int beg = g_off[node], end = g_off[node + 1];
    for (int base = beg; base < end; base += 32) {
        int m = min(32, end - base);
        int2 c = make_int2(0, node);         // norm=0, src=node (safe pad)
        if (lane < m) c = __ldg(&g_csr[base + lane]);
        int iters = (m + 3) >> 2;
#pragma unroll 4
        for (int it = 0; it < iters; it++) {
            int esel = it * 4 + g;           // <= 31 always
            float nb = __int_as_float(__shfl_sync(0xffffffffu, c.x, esel));
            int   sb = __shfl_sync(0xffffffffu, c.y, esel);
            float4 v = __ldg(&Hin4[sb * 8 + q]);
            acc.x = fmaf(nb, v.x, acc.x);
            acc.y = fmaf(nb, v.y, acc.y);
            acc.z = fmaf(nb, v.z, acc.z);
            acc.w = fmaf(nb, v.w, acc.w);
        }
    }
    // reduce the 4 edge subgroups (lanes with equal q end identical)
#pragma unroll
    for (int o = 8; o < 32; o <<= 1) {
        acc.x += __shfl_xor_sync(0xffffffffu, acc.x, o);
        acc.y += __shfl_xor_sync(0xffffffffu, acc.y, o);
        acc.z += __shfl_xor_sync(0xffffffffu, acc.z, o);
        acc.w += __shfl_xor_sync(0xffffffffu, acc.w, o);
    }
    return acc;
}

// ---------------- conv layers (NPB nodes per block, W column in registers) --
__global__ __launch_bounds__(256) void conv1_k(const float* __restrict__ W,
                                               const float* __restrict__ b,
                                               const float* __restrict__ tarr,
                                               int step) {
    __shared__ float sAgg[8][32];
    int tid = threadIdx.x, w = tid >> 5, lane = tid & 31;
    float wcol[32];
#pragma unroll
    for (int c = 0; c < 32; c++) wcol[c] = __ldg(&W[c * 32 + lane]);
    float bias = __ldg(&b[lane]);
    float wx = wcol[26] + wcol[27] + wcol[28];
    float wt = wcol[29] + wcol[30] + wcol[31];
    float tv = __ldg(&tarr[step]);
    const float4* H4 = (const float4*)g_H;
#pragma unroll 1
    for (int i = 0; i < NPB / 8; i++) {
        int node = blockIdx.x * NPB + i * 8 + w;
        float4 a = gather4(H4, node, lane);
        if (lane < 8) *(float4*)&sAgg[w][lane * 4] = a;
        __syncwarp();
        float o = bias;
#pragma unroll
        for (int c = 0; c < 32; c++) o = fmaf(sAgg[w][c], wcol[c], o);
        o = fmaf(g_xa[node], wx, o);
        o = fmaf(tv * g_sn[node], wt, o);
        g_H1[node * 32 + lane] = fmaxf(o, 0.f);
        __syncwarp();
    }
}

__global__ __launch_bounds__(256) void conv2_k(const float* __restrict__ W,
                                               const float* __restrict__ b) {
    __shared__ float sAgg[8][32];
    int tid = threadIdx.x, w = tid >> 5, lane = tid & 31;
    float wcol[32];
#pragma unroll
    for (int c = 0; c < 32; c++) wcol[c] = __ldg(&W[c * 32 + lane]);
    float bias = __ldg(&b[lane]);
    const float4* H4 = (const float4*)g_H1;
#pragma unroll 1
    for (int i = 0; i < NPB / 8; i++) {
        int node = blockIdx.x * NPB + i * 8 + w;
        float4 a = gather4(H4, node, lane);
        if (lane < 8) *(float4*)&sAgg[w][lane * 4] = a;
        __syncwarp();
        float o = bias;
#pragma unroll
        for (int c = 0; c < 32; c++) o = fmaf(sAgg[w][c], wcol[c], o);
        g_H2[node * 32 + lane] = fmaxf(o, 0.f);
        __syncwarp();
    }
}

// conv3 (32->26) fused with fc3(26->32)+relu+fc4(32->1) readout
__global__ __launch_bounds__(256) void conv3_k(const float* __restrict__ W,
                                               const float* __restrict__ b,
                                               const float* __restrict__ f3w,
                                               const float* __restrict__ f3b,
                                               const float* __restrict__ f4w,
                                               const float* __restrict__ f4b,
                                               float* __restrict__ out, int step) {
    __shared__ float sAgg[8][32], sF3[832];
    int tid = threadIdx.x, w = tid >> 5, lane = tid & 31;
    for (int i = tid; i < 832; i += 256) sF3[i] = f3w[i];
    float wcol[32];
#pragma unroll
    for (int c = 0; c < 32; c++)
        wcol[c] = (lane < 26) ? __ldg(&W[c * 26 + lane]) : 0.f;
    float bias = (lane < 26) ? __ldg(&b[lane]) : 0.f;
    float b3 = __ldg(&f3b[lane]);
    float w4 = __ldg(&f4w[lane]);
    float b4 = __ldg(&f4b[0]);
    const float4* H4 = (const float4*)g_H2;
    __syncthreads();
#pragma unroll 1
    for (int i = 0; i < NPB / 8; i++) {
        int node = blockIdx.x * NPB + i * 8 + w;
        float4 a = gather4(H4, node, lane);
        if (lane < 8) *(float4*)&sAgg[w][lane * 4] = a;
        __syncwarp();
        float o = bias;
#pragma unroll
        for (int c = 0; c < 32; c++) o = fmaf(sAgg[w][c], wcol[c], o);
        float h3 = fmaxf(o, 0.f);                  // lanes >= 26 -> 0
        if (lane < 26) g_H[node * 32 + lane] = h3; // next recurrent state
        __syncwarp();
        sAgg[w][lane] = (lane < 26) ? h3 : 0.f;
        __syncwarp();
        float z = b3;
#pragma unroll
        for (int j = 0; j < 26; j++) z = fmaf(sAgg[w][j], sF3[j * 32 + lane], z);
        z = fmaxf(z, 0.f);
        float p = z * w4;
#pragma unroll
        for (int o2 = 16; o2; o2 >>= 1) p += __shfl_down_sync(0xffffffffu, p, o2);
        if (lane == 0) out[step * NN + node] = p + b4;
        __syncwarp();
    }
}

// ---------------- launcher --------------------------------------------------
extern "C" void kernel_launch(void* const* d_in, const int* in_sizes, int n_in,
                              void* d_out, int out_size) {
    const float* x  = (const float*)d_in[0];
    const float* t  = (const float*)d_in[1];
    const float* y  = (const float*)d_in[2];
    const void*  ei = d_in[3];                 // int32 or int64 — probed on device
    const float* fc1W = (const float*)d_in[4];
    const float* fc1b = (const float*)d_in[5];
    const float* fc2W = (const float*)d_in[6];
    const float* fc2b = (const float*)d_in[7];
    const float* c1W  = (const float*)d_in[8];
    const float* c1b  = (const float*)d_in[9];
    const float* c2W  = (const float*)d_in[10];
    const float* c2b  = (const float*)d_in[11];
    const float* c3W  = (const float*)d_in[12];
    const float* c3b  = (const float*)d_in[13];
    const float* f3W  = (const float*)d_in[14];
    const float* f3b  = (const float*)d_in[15];
    const float* f4W  = (const float*)d_in[16];
    const float* f4b  = (const float*)d_in[17];
    float* out = (float*)d_out;

    int T = in_sizes[1];
    int E = in_sizes[3] / 2;

    // ---- per-call preprocessing: dtype probe, CSR build, invariants ----
    detect_k<<<1, 1>>>(ei);
    zero_k<<<(NN + 255) / 256, 256>>>();
    count_k<<<(E + 255) / 256, 256>>>(ei, E);
    deg_k<<<(NN + 255) / 256, 256>>>();
    scan1_k<<<NSCAN, SCAN_BLK>>>();
    scan2_k<<<1, 256>>>(NSCAN);
    scan3_k<<<NSCAN, SCAN_BLK>>>();
    scatter_k<<<(E + 255) / 256, 256>>>(ei, E);
    xasn_k<<<(NN * 32 + 255) / 256, 256>>>(x);
    inith_k<<<(NN + 255) / 256, 256>>>(y, fc1W, fc1b, fc2W, fc2b);
    row0_k<<<(NN + 255) / 256, 256>>>(out, y);

    // ---- 49 recurrent steps, 3 fused GCN kernels each ----
    int grid = NN / NPB;                       // 3125, exact
    for (int s = 1; s < T; s++) {
        conv1_k<<<grid, 256>>>(c1W, c1b, t, s);
        conv2_k<<<grid, 256>>>(c2W, c2b);
        conv3_k<<<grid, 256>>>(c3W, c3b, f3W, f3b, f4W, f4b, out, s);
    }
}